// round 6
// baseline (speedup 1.0000x reference)
#include <cuda_runtime.h>
#include <math_constants.h>

#define NB 4096
#define NC 1000
#define ND 2048
#define CP 1024
#define TILE 64
#define NTILE (CP / TILE)                 // 16
#define NPAIRS (NTILE * (NTILE + 1) / 2)  // 136

// Scratch (device globals — no allocation allowed)
__device__ float g_dist[CP * CP];   // Dist[i*CP + j], only i,j < NC valid
__device__ float g_sq[CP];          // raw row norms sum(W[c,:]^2)
__device__ float g_ymax[NB];
__device__ int   g_j0[NB];

// ---------------------------------------------------------------------------
// Kernel 1: per-row argmax + max of prediction
// ---------------------------------------------------------------------------
__global__ void __launch_bounds__(128) argmax_kernel(const float* __restrict__ pred) {
    int b = blockIdx.x;
    const float* row = pred + (long)b * NC;
    float best = -CUDART_INF_F;
    int bidx = NC;
    for (int c = threadIdx.x; c < NC; c += 128) {
        float v = row[c];
        if (v > best) { best = v; bidx = c; }   // strided: lower c seen first per thread
    }
    for (int o = 16; o > 0; o >>= 1) {
        float v2 = __shfl_down_sync(0xFFFFFFFFu, best, o);
        int   i2 = __shfl_down_sync(0xFFFFFFFFu, bidx, o);
        if (v2 > best || (v2 == best && i2 < bidx)) { best = v2; bidx = i2; }
    }
    __shared__ float sv[4];
    __shared__ int   si[4];
    int w = threadIdx.x >> 5;
    if ((threadIdx.x & 31) == 0) { sv[w] = best; si[w] = bidx; }
    __syncthreads();
    if (threadIdx.x == 0) {
        for (int i = 1; i < 4; i++) {
            if (sv[i] > best || (sv[i] == best && si[i] < bidx)) { best = sv[i]; bidx = si[i]; }
        }
        g_ymax[b] = best;
        g_j0[b] = bidx;
    }
}

// ---------------------------------------------------------------------------
// Kernel 2: raw row norms of W (no k^2 scaling; applied in dist epilogue)
// ---------------------------------------------------------------------------
__global__ void __launch_bounds__(256) norms_kernel(const float* __restrict__ W) {
    int c = blockIdx.x;
    const float* row = W + (long)c * ND;
    float s = 0.f;
    for (int d = threadIdx.x * 4; d < ND; d += 256 * 4) {
        float4 v = *(const float4*)(row + d);
        s += v.x * v.x + v.y * v.y + v.z * v.z + v.w * v.w;
    }
    for (int o = 16; o > 0; o >>= 1) s += __shfl_down_sync(0xFFFFFFFFu, s, o);
    __shared__ float sm[8];
    int w = threadIdx.x >> 5;
    if ((threadIdx.x & 31) == 0) sm[w] = s;
    __syncthreads();
    if (threadIdx.x == 0) {
        float t = 0.f;
        for (int i = 0; i < 8; i++) t += sm[i];
        g_sq[c] = t;
    }
}

// ---------------------------------------------------------------------------
// Kernel 3: triangular Gram G = W W^T (64x64 tiles), fused distance epilogue
//   Dist[i,j] = k * sqrt(max(sq_i + sq_j - 2*G_ij, 0)), written symmetrically
// ---------------------------------------------------------------------------
__global__ void __launch_bounds__(256) gram_dist_kernel(const float* __restrict__ W,
                                                        const float* __restrict__ Kin) {
    // map linear block id -> upper-triangular tile pair (ti <= tj)
    int p = blockIdx.x;
    int ti = 0;
    while (p >= NTILE - ti) { p -= NTILE - ti; ti++; }
    int tj = ti + p;

    __shared__ float As[32][TILE];  // [k][row]  (transposed for conflict-free reads)
    __shared__ float Bs[32][TILE];

    int tid = threadIdx.x;
    int tx = tid & 15, ty = tid >> 4;
    int rowA = ti * TILE, rowB = tj * TILE;

    float acc[4][4] = {};

    for (int k0 = 0; k0 < ND; k0 += 32) {
        #pragma unroll
        for (int l = tid; l < 512; l += 256) {
            int r = l >> 3, q = l & 7;
            int gr = rowA + r;
            float4 v = make_float4(0.f, 0.f, 0.f, 0.f);
            if (gr < NC) v = *(const float4*)(W + (long)gr * ND + k0 + q * 4);
            As[q * 4 + 0][r] = v.x; As[q * 4 + 1][r] = v.y;
            As[q * 4 + 2][r] = v.z; As[q * 4 + 3][r] = v.w;
        }
        #pragma unroll
        for (int l = tid; l < 512; l += 256) {
            int r = l >> 3, q = l & 7;
            int gr = rowB + r;
            float4 v = make_float4(0.f, 0.f, 0.f, 0.f);
            if (gr < NC) v = *(const float4*)(W + (long)gr * ND + k0 + q * 4);
            Bs[q * 4 + 0][r] = v.x; Bs[q * 4 + 1][r] = v.y;
            Bs[q * 4 + 2][r] = v.z; Bs[q * 4 + 3][r] = v.w;
        }
        __syncthreads();
        #pragma unroll
        for (int kk = 0; kk < 32; kk++) {
            float4 a = *(const float4*)&As[kk][ty * 4];
            float4 b = *(const float4*)&Bs[kk][tx * 4];
            acc[0][0] += a.x * b.x; acc[0][1] += a.x * b.y; acc[0][2] += a.x * b.z; acc[0][3] += a.x * b.w;
            acc[1][0] += a.y * b.x; acc[1][1] += a.y * b.y; acc[1][2] += a.y * b.z; acc[1][3] += a.y * b.w;
            acc[2][0] += a.z * b.x; acc[2][1] += a.z * b.y; acc[2][2] += a.z * b.z; acc[2][3] += a.z * b.w;
            acc[3][0] += a.w * b.x; acc[3][1] += a.w * b.y; acc[3][2] += a.w * b.z; acc[3][3] += a.w * b.w;
        }
        __syncthreads();
    }

    // epilogue: distances, written to both (i,j) and (j,i)
    const float DS = (float)(1.0 / (double)0.224f);   // matches float32(0.224) min-std path
    float kscale = Kin[0] * DS;

    float sqa[4], sqb[4];
    #pragma unroll
    for (int i = 0; i < 4; i++) {
        int gi = rowA + ty * 4 + i;
        sqa[i] = (gi < NC) ? g_sq[gi] : 0.f;
        int gj = rowB + tx * 4 + i;
        sqb[i] = (gj < NC) ? g_sq[gj] : 0.f;
    }
    #pragma unroll
    for (int i = 0; i < 4; i++) {
        int gi = rowA + ty * 4 + i;
        if (gi >= NC) continue;
        #pragma unroll
        for (int j = 0; j < 4; j++) {
            int gj = rowB + tx * 4 + j;
            if (gj >= NC) continue;
            float d2 = sqa[i] + sqb[j] - 2.f * acc[i][j];
            float d = kscale * sqrtf(fmaxf(d2, 0.f));
            g_dist[gi * CP + gj] = d;
            g_dist[gj * CP + gi] = d;
        }
    }
}

// ---------------------------------------------------------------------------
// Kernel 4: out[b] = min_{c != j0} (ymax[b] - pred[b,c]) / Dist[j0[b], c]
// ---------------------------------------------------------------------------
__global__ void __launch_bounds__(128) final_kernel(const float* __restrict__ pred,
                                                    float* __restrict__ out) {
    int b = blockIdx.x;
    int j0 = g_j0[b];
    float ym = g_ymax[b];
    const float* dr = g_dist + (long)j0 * CP;
    const float* pr = pred + (long)b * NC;
    float mn = CUDART_INF_F;
    for (int c = threadIdx.x; c < NC; c += 128) {
        if (c == j0) continue;
        float r = (ym - pr[c]) / dr[c];
        mn = fminf(mn, r);
    }
    for (int o = 16; o > 0; o >>= 1)
        mn = fminf(mn, __shfl_down_sync(0xFFFFFFFFu, mn, o));
    __shared__ float sm[4];
    int w = threadIdx.x >> 5;
    if ((threadIdx.x & 31) == 0) sm[w] = mn;
    __syncthreads();
    if (threadIdx.x == 0) {
        out[b] = fminf(fminf(sm[0], sm[1]), fminf(sm[2], sm[3]));
    }
}

// ---------------------------------------------------------------------------
extern "C" void kernel_launch(void* const* d_in, const int* in_sizes, int n_in,
                              void* d_out, int out_size) {
    const float* pred = (const float*)d_in[0];
    const float* W    = (const float*)d_in[1];
    const float* K    = (const float*)d_in[2];
    float* out = (float*)d_out;

    argmax_kernel<<<NB, 128>>>(pred);
    norms_kernel<<<NC, 256>>>(W);
    gram_dist_kernel<<<NPAIRS, 256>>>(W, K);
    final_kernel<<<NB, 128>>>(pred, out);
}

// round 7
// speedup vs baseline: 1.0028x; 1.0028x over previous
#include <cuda_runtime.h>
#include <math_constants.h>

#define NB 4096
#define NC 1000
#define ND 2048
#define CP 1024
#define TILE 64
#define NTILE (CP / TILE)                 // 16
#define NPAIRS (NTILE * (NTILE + 1) / 2)  // 136

// Scratch (device globals — no allocation allowed)
__device__ float g_dist[CP * CP];   // Dist[i*CP + j], only i,j < NC valid
__device__ float g_sq[CP];          // raw row norms sum(W[c,:]^2)
__device__ float g_ymax[NB];
__device__ int   g_j0[NB];

// ---------------------------------------------------------------------------
// Kernel 1: per-row argmax + max of prediction
// ---------------------------------------------------------------------------
__global__ void __launch_bounds__(128) argmax_kernel(const float* __restrict__ pred) {
    int b = blockIdx.x;
    const float* row = pred + (long)b * NC;
    float best = -CUDART_INF_F;
    int bidx = NC;
    for (int c = threadIdx.x; c < NC; c += 128) {
        float v = row[c];
        if (v > best) { best = v; bidx = c; }   // strided: lower c seen first per thread
    }
    for (int o = 16; o > 0; o >>= 1) {
        float v2 = __shfl_down_sync(0xFFFFFFFFu, best, o);
        int   i2 = __shfl_down_sync(0xFFFFFFFFu, bidx, o);
        if (v2 > best || (v2 == best && i2 < bidx)) { best = v2; bidx = i2; }
    }
    __shared__ float sv[4];
    __shared__ int   si[4];
    int w = threadIdx.x >> 5;
    if ((threadIdx.x & 31) == 0) { sv[w] = best; si[w] = bidx; }
    __syncthreads();
    if (threadIdx.x == 0) {
        for (int i = 1; i < 4; i++) {
            if (sv[i] > best || (sv[i] == best && si[i] < bidx)) { best = sv[i]; bidx = si[i]; }
        }
        g_ymax[b] = best;
        g_j0[b] = bidx;
    }
}

// ---------------------------------------------------------------------------
// Kernel 2: raw row norms of W (no k^2 scaling; applied in dist epilogue)
// ---------------------------------------------------------------------------
__global__ void __launch_bounds__(256) norms_kernel(const float* __restrict__ W) {
    int c = blockIdx.x;
    const float* row = W + (long)c * ND;
    float s = 0.f;
    for (int d = threadIdx.x * 4; d < ND; d += 256 * 4) {
        float4 v = *(const float4*)(row + d);
        s += v.x * v.x + v.y * v.y + v.z * v.z + v.w * v.w;
    }
    for (int o = 16; o > 0; o >>= 1) s += __shfl_down_sync(0xFFFFFFFFu, s, o);
    __shared__ float sm[8];
    int w = threadIdx.x >> 5;
    if ((threadIdx.x & 31) == 0) sm[w] = s;
    __syncthreads();
    if (threadIdx.x == 0) {
        float t = 0.f;
        for (int i = 0; i < 8; i++) t += sm[i];
        g_sq[c] = t;
    }
}

// ---------------------------------------------------------------------------
// Kernel 3: triangular Gram G = W W^T (64x64 tiles), fused distance epilogue
//   Dist[i,j] = k * sqrt(max(sq_i + sq_j - 2*G_ij, 0)), written symmetrically
// ---------------------------------------------------------------------------
__global__ void __launch_bounds__(256) gram_dist_kernel(const float* __restrict__ W,
                                                        const float* __restrict__ Kin) {
    // map linear block id -> upper-triangular tile pair (ti <= tj)
    int p = blockIdx.x;
    int ti = 0;
    while (p >= NTILE - ti) { p -= NTILE - ti; ti++; }
    int tj = ti + p;

    __shared__ float As[32][TILE];  // [k][row]  (transposed for conflict-free reads)
    __shared__ float Bs[32][TILE];

    int tid = threadIdx.x;
    int tx = tid & 15, ty = tid >> 4;
    int rowA = ti * TILE, rowB = tj * TILE;

    float acc[4][4] = {};

    for (int k0 = 0; k0 < ND; k0 += 32) {
        #pragma unroll
        for (int l = tid; l < 512; l += 256) {
            int r = l >> 3, q = l & 7;
            int gr = rowA + r;
            float4 v = make_float4(0.f, 0.f, 0.f, 0.f);
            if (gr < NC) v = *(const float4*)(W + (long)gr * ND + k0 + q * 4);
            As[q * 4 + 0][r] = v.x; As[q * 4 + 1][r] = v.y;
            As[q * 4 + 2][r] = v.z; As[q * 4 + 3][r] = v.w;
        }
        #pragma unroll
        for (int l = tid; l < 512; l += 256) {
            int r = l >> 3, q = l & 7;
            int gr = rowB + r;
            float4 v = make_float4(0.f, 0.f, 0.f, 0.f);
            if (gr < NC) v = *(const float4*)(W + (long)gr * ND + k0 + q * 4);
            Bs[q * 4 + 0][r] = v.x; Bs[q * 4 + 1][r] = v.y;
            Bs[q * 4 + 2][r] = v.z; Bs[q * 4 + 3][r] = v.w;
        }
        __syncthreads();
        #pragma unroll
        for (int kk = 0; kk < 32; kk++) {
            float4 a = *(const float4*)&As[kk][ty * 4];
            float4 b = *(const float4*)&Bs[kk][tx * 4];
            acc[0][0] += a.x * b.x; acc[0][1] += a.x * b.y; acc[0][2] += a.x * b.z; acc[0][3] += a.x * b.w;
            acc[1][0] += a.y * b.x; acc[1][1] += a.y * b.y; acc[1][2] += a.y * b.z; acc[1][3] += a.y * b.w;
            acc[2][0] += a.z * b.x; acc[2][1] += a.z * b.y; acc[2][2] += a.z * b.z; acc[2][3] += a.z * b.w;
            acc[3][0] += a.w * b.x; acc[3][1] += a.w * b.y; acc[3][2] += a.w * b.z; acc[3][3] += a.w * b.w;
        }
        __syncthreads();
    }

    // epilogue: distances, written to both (i,j) and (j,i)
    const float DS = (float)(1.0 / (double)0.224f);   // matches float32(0.224) min-std path
    float kscale = Kin[0] * DS;

    float sqa[4], sqb[4];
    #pragma unroll
    for (int i = 0; i < 4; i++) {
        int gi = rowA + ty * 4 + i;
        sqa[i] = (gi < NC) ? g_sq[gi] : 0.f;
        int gj = rowB + tx * 4 + i;
        sqb[i] = (gj < NC) ? g_sq[gj] : 0.f;
    }
    #pragma unroll
    for (int i = 0; i < 4; i++) {
        int gi = rowA + ty * 4 + i;
        if (gi >= NC) continue;
        #pragma unroll
        for (int j = 0; j < 4; j++) {
            int gj = rowB + tx * 4 + j;
            if (gj >= NC) continue;
            float d2 = sqa[i] + sqb[j] - 2.f * acc[i][j];
            float d = kscale * sqrtf(fmaxf(d2, 0.f));
            g_dist[gi * CP + gj] = d;
            g_dist[gj * CP + gi] = d;
        }
    }
}

// ---------------------------------------------------------------------------
// Kernel 4: out[b] = min_{c != j0} (ymax[b] - pred[b,c]) / Dist[j0[b], c]
// ---------------------------------------------------------------------------
__global__ void __launch_bounds__(128) final_kernel(const float* __restrict__ pred,
                                                    float* __restrict__ out) {
    int b = blockIdx.x;
    int j0 = g_j0[b];
    float ym = g_ymax[b];
    const float* dr = g_dist + (long)j0 * CP;
    const float* pr = pred + (long)b * NC;
    float mn = CUDART_INF_F;
    for (int c = threadIdx.x; c < NC; c += 128) {
        if (c == j0) continue;
        float r = (ym - pr[c]) / dr[c];
        mn = fminf(mn, r);
    }
    for (int o = 16; o > 0; o >>= 1)
        mn = fminf(mn, __shfl_down_sync(0xFFFFFFFFu, mn, o));
    __shared__ float sm[4];
    int w = threadIdx.x >> 5;
    if ((threadIdx.x & 31) == 0) sm[w] = mn;
    __syncthreads();
    if (threadIdx.x == 0) {
        out[b] = fminf(fminf(sm[0], sm[1]), fminf(sm[2], sm[3]));
    }
}

// ---------------------------------------------------------------------------
extern "C" void kernel_launch(void* const* d_in, const int* in_sizes, int n_in,
                              void* d_out, int out_size) {
    const float* pred = (const float*)d_in[0];
    const float* W    = (const float*)d_in[1];
    const float* K    = (const float*)d_in[2];
    float* out = (float*)d_out;

    argmax_kernel<<<NB, 128>>>(pred);
    norms_kernel<<<NC, 256>>>(W);
    gram_dist_kernel<<<NPAIRS, 256>>>(W, K);
    final_kernel<<<NB, 128>>>(pred, out);
}

// round 8
// speedup vs baseline: 3.5530x; 3.5431x over previous
#include <cuda_runtime.h>
#include <cuda_bf16.h>
#include <math_constants.h>
#include <cstdint>

#define NB 4096
#define NC 1000
#define ND 2048
#define CP 1024
#define TILE 64
#define NTILE (CP / TILE)                 // 16
#define NPAIRS (NTILE * (NTILE + 1) / 2)  // 136
#define KC 64                             // k-chunk per smem stage
#define APITCH 72                         // smem row pitch in halves (144B: conflict-free ldmatrix)

// Scratch (device globals — no allocation allowed)
__device__ __align__(16) __nv_bfloat16 g_Wbf[CP * ND];  // 4MB bf16 copy of W (zero-padded rows)
__device__ float g_rdist[CP * CP];  // 1/(k*dist[i,j]); only i,j < NC meaningful
__device__ float g_sq[CP];          // row norms of bf16-rounded W

// ---------------------------------------------------------------------------
// PTX helpers
// ---------------------------------------------------------------------------
__device__ __forceinline__ void ldsm_x4(uint32_t &r0, uint32_t &r1, uint32_t &r2, uint32_t &r3,
                                        uint32_t addr) {
    asm volatile("ldmatrix.sync.aligned.m8n8.x4.shared.b16 {%0,%1,%2,%3}, [%4];"
                 : "=r"(r0), "=r"(r1), "=r"(r2), "=r"(r3) : "r"(addr));
}

__device__ __forceinline__ void mma16816(float *c, uint32_t a0, uint32_t a1, uint32_t a2,
                                         uint32_t a3, uint32_t b0, uint32_t b1) {
    asm volatile(
        "mma.sync.aligned.m16n8k16.row.col.f32.bf16.bf16.f32 "
        "{%0,%1,%2,%3}, {%4,%5,%6,%7}, {%8,%9}, {%0,%1,%2,%3};"
        : "+f"(c[0]), "+f"(c[1]), "+f"(c[2]), "+f"(c[3])
        : "r"(a0), "r"(a1), "r"(a2), "r"(a3), "r"(b0), "r"(b1));
}

// ---------------------------------------------------------------------------
// Kernel 1: convert W -> bf16 (zero-pad rows NC..CP) + row norms of rounded W
// ---------------------------------------------------------------------------
__global__ void __launch_bounds__(256) convert_kernel(const float* __restrict__ W) {
    int c = blockIdx.x;
    int tid = threadIdx.x;
    union { uint4 u; __nv_bfloat16 h[8]; } pk;
    float s = 0.f;
    if (c < NC) {
        const float4* src = (const float4*)(W + (long)c * ND);
        float4 v0 = src[tid * 2 + 0];
        float4 v1 = src[tid * 2 + 1];
        pk.h[0] = __float2bfloat16_rn(v0.x); pk.h[1] = __float2bfloat16_rn(v0.y);
        pk.h[2] = __float2bfloat16_rn(v0.z); pk.h[3] = __float2bfloat16_rn(v0.w);
        pk.h[4] = __float2bfloat16_rn(v1.x); pk.h[5] = __float2bfloat16_rn(v1.y);
        pk.h[6] = __float2bfloat16_rn(v1.z); pk.h[7] = __float2bfloat16_rn(v1.w);
        #pragma unroll
        for (int i = 0; i < 8; i++) {
            float f = __bfloat162float(pk.h[i]);
            s += f * f;
        }
    } else {
        pk.u = make_uint4(0, 0, 0, 0);
    }
    *(uint4*)(g_Wbf + (long)c * ND + tid * 8) = pk.u;

    for (int o = 16; o > 0; o >>= 1) s += __shfl_down_sync(0xFFFFFFFFu, s, o);
    __shared__ float sm[8];
    int w = tid >> 5;
    if ((tid & 31) == 0) sm[w] = s;
    __syncthreads();
    if (tid == 0) {
        float t = 0.f;
        for (int i = 0; i < 8; i++) t += sm[i];
        g_sq[c] = t;
    }
}

// ---------------------------------------------------------------------------
// Kernel 2: triangular Gram via bf16 tensor-core MMA, fused reciprocal-distance
//   epilogue: g_rdist[i,j] = 1 / (k * sqrt(max(sq_i + sq_j - 2*G_ij, 0)))
// ---------------------------------------------------------------------------
__global__ void __launch_bounds__(256) gram_mma_kernel(const float* __restrict__ Kin) {
    // linear block id -> upper-triangular tile pair (ti <= tj)
    int p = blockIdx.x;
    int ti = 0;
    while (p >= NTILE - ti) { p -= NTILE - ti; ti++; }
    int tj = ti + p;
    int rowA = ti * TILE, rowB = tj * TILE;

    __shared__ __align__(16) __nv_bfloat16 sA[2][TILE * APITCH];
    __shared__ __align__(16) __nv_bfloat16 sB[2][TILE * APITCH];

    int tid = threadIdx.x;
    int wid = tid >> 5, lane = tid & 31;
    int wr = wid & 3;        // 4 row-strips of 16
    int wc = wid >> 2;       // 2 col-strips of 32

    uint32_t sA0 = (uint32_t)__cvta_generic_to_shared(sA[0]);
    uint32_t sA1 = (uint32_t)__cvta_generic_to_shared(sA[1]);
    uint32_t sB0 = (uint32_t)__cvta_generic_to_shared(sB[0]);
    uint32_t sB1 = (uint32_t)__cvta_generic_to_shared(sB[1]);

    // ldmatrix lane address offsets (halves)
    int arow = wr * 16 + (lane & 15);
    int acol = (lane >> 4) << 3;
    uint32_t aOff = (uint32_t)(arow * APITCH + acol) * 2u;
    int brow = wc * 32 + (lane & 7) + ((lane >> 4) << 3);
    int bcol = ((lane >> 3) & 1) << 3;
    uint32_t bOff = (uint32_t)(brow * APITCH + bcol) * 2u;

    // global load assignment: 4 x 16B chunks per thread per stage
    int ldg_tile[4], ldg_row[4], ldg_sub[4];
    #pragma unroll
    for (int t = 0; t < 4; t++) {
        ldg_tile[t] = t >> 1;
        ldg_row[t]  = ((t & 1) << 5) + (tid >> 3);
        ldg_sub[t]  = tid & 7;
    }

    float acc[4][4] = {};
    uint4 fetch[4];

    // prologue: stage 0
    #pragma unroll
    for (int t = 0; t < 4; t++) {
        const __nv_bfloat16* gp = g_Wbf +
            (long)((ldg_tile[t] ? rowB : rowA) + ldg_row[t]) * ND + ldg_sub[t] * 8;
        fetch[t] = *(const uint4*)gp;
    }
    #pragma unroll
    for (int t = 0; t < 4; t++) {
        __nv_bfloat16* dp = (ldg_tile[t] ? sB[0] : sA[0]) + ldg_row[t] * APITCH + ldg_sub[t] * 8;
        *(uint4*)dp = fetch[t];
    }
    __syncthreads();

    const int NSTAGE = ND / KC;  // 32
    for (int s = 0; s < NSTAGE; s++) {
        if (s + 1 < NSTAGE) {
            int k0 = (s + 1) * KC;
            #pragma unroll
            for (int t = 0; t < 4; t++) {
                const __nv_bfloat16* gp = g_Wbf +
                    (long)((ldg_tile[t] ? rowB : rowA) + ldg_row[t]) * ND + k0 + ldg_sub[t] * 8;
                fetch[t] = *(const uint4*)gp;
            }
        }

        int buf = s & 1;
        uint32_t aBase  = (buf ? sA1 : sA0) + aOff;
        uint32_t bBase0 = (buf ? sB1 : sB0) + bOff;
        uint32_t bBase1 = bBase0 + 16 * APITCH * 2;

        #pragma unroll
        for (int kk = 0; kk < 4; kk++) {
            uint32_t a0, a1, a2, a3;
            ldsm_x4(a0, a1, a2, a3, aBase + kk * 32);
            uint32_t b0, b1, b2, b3, b4, b5, b6, b7;
            ldsm_x4(b0, b1, b2, b3, bBase0 + kk * 32);
            ldsm_x4(b4, b5, b6, b7, bBase1 + kk * 32);
            mma16816(acc[0], a0, a1, a2, a3, b0, b1);
            mma16816(acc[1], a0, a1, a2, a3, b2, b3);
            mma16816(acc[2], a0, a1, a2, a3, b4, b5);
            mma16816(acc[3], a0, a1, a2, a3, b6, b7);
        }

        if (s + 1 < NSTAGE) {
            int nbuf = (s + 1) & 1;
            #pragma unroll
            for (int t = 0; t < 4; t++) {
                __nv_bfloat16* dp = (ldg_tile[t] ? sB[nbuf] : sA[nbuf]) +
                                    ldg_row[t] * APITCH + ldg_sub[t] * 8;
                *(uint4*)dp = fetch[t];
            }
        }
        __syncthreads();
    }

    // epilogue: reciprocal distances, symmetric write
    const float DS = (float)(1.0 / (double)0.224f);
    float invk = 1.0f / (Kin[0] * DS);

    int g = lane >> 2, tg = lane & 3;
    int gi0 = rowA + wr * 16 + g;
    int gi1 = gi0 + 8;
    float sqi0 = g_sq[gi0], sqi1 = g_sq[gi1];

    #pragma unroll
    for (int t = 0; t < 4; t++) {
        int gj = rowB + wc * 32 + t * 8 + tg * 2;
        float sqj0 = g_sq[gj], sqj1 = g_sq[gj + 1];
        float d2, rv;
        d2 = sqi0 + sqj0 - 2.f * acc[t][0];
        rv = rsqrtf(fmaxf(d2, 0.f)) * invk;
        g_rdist[gi0 * CP + gj] = rv;  g_rdist[gj * CP + gi0] = rv;
        d2 = sqi0 + sqj1 - 2.f * acc[t][1];
        rv = rsqrtf(fmaxf(d2, 0.f)) * invk;
        g_rdist[gi0 * CP + gj + 1] = rv;  g_rdist[(gj + 1) * CP + gi0] = rv;
        d2 = sqi1 + sqj0 - 2.f * acc[t][2];
        rv = rsqrtf(fmaxf(d2, 0.f)) * invk;
        g_rdist[gi1 * CP + gj] = rv;  g_rdist[gj * CP + gi1] = rv;
        d2 = sqi1 + sqj1 - 2.f * acc[t][3];
        rv = rsqrtf(fmaxf(d2, 0.f)) * invk;
        g_rdist[gi1 * CP + gj + 1] = rv;  g_rdist[(gj + 1) * CP + gi1] = rv;
    }
}

// ---------------------------------------------------------------------------
// Kernel 3: fused argmax + min-ratio. Prediction row cached in smem.
//   out[b] = min_{c != j0} (ymax - pred[b,c]) * g_rdist[j0, c]
// ---------------------------------------------------------------------------
__global__ void __launch_bounds__(256) fused_final_kernel(const float* __restrict__ pred,
                                                          float* __restrict__ out) {
    __shared__ float4 sp[250];
    __shared__ float swv[8];
    __shared__ int   swi[8];
    __shared__ float s_ym;
    __shared__ int   s_j0;

    int b = blockIdx.x, tid = threadIdx.x;
    int w = tid >> 5, lane = tid & 31;

    float best = -CUDART_INF_F;
    int bidx = NC;
    if (tid < 250) {
        float4 v = ((const float4*)(pred + (long)b * NC))[tid];
        sp[tid] = v;
        int c = tid * 4;
        if (v.x > best) { best = v.x; bidx = c; }
        if (v.y > best) { best = v.y; bidx = c + 1; }
        if (v.z > best) { best = v.z; bidx = c + 2; }
        if (v.w > best) { best = v.w; bidx = c + 3; }
    }
    for (int o = 16; o > 0; o >>= 1) {
        float v2 = __shfl_down_sync(0xFFFFFFFFu, best, o);
        int   i2 = __shfl_down_sync(0xFFFFFFFFu, bidx, o);
        if (v2 > best || (v2 == best && i2 < bidx)) { best = v2; bidx = i2; }
    }
    if (lane == 0) { swv[w] = best; swi[w] = bidx; }
    __syncthreads();
    if (tid == 0) {
        for (int i = 1; i < 8; i++) {
            if (swv[i] > best || (swv[i] == best && swi[i] < bidx)) { best = swv[i]; bidx = swi[i]; }
        }
        s_ym = best;
        s_j0 = bidx;
    }
    __syncthreads();

    float ym = s_ym;
    int j0 = s_j0;

    float mn = CUDART_INF_F;
    if (tid < 250) {
        float4 d = ((const float4*)(g_rdist + (long)j0 * CP))[tid];
        float4 v = sp[tid];
        int c = tid * 4;
        float r0 = (c     == j0) ? CUDART_INF_F : (ym - v.x) * d.x;
        float r1 = (c + 1 == j0) ? CUDART_INF_F : (ym - v.y) * d.y;
        float r2 = (c + 2 == j0) ? CUDART_INF_F : (ym - v.z) * d.z;
        float r3 = (c + 3 == j0) ? CUDART_INF_F : (ym - v.w) * d.w;
        mn = fminf(fminf(r0, r1), fminf(r2, r3));
    }
    for (int o = 16; o > 0; o >>= 1)
        mn = fminf(mn, __shfl_down_sync(0xFFFFFFFFu, mn, o));
    if (lane == 0) swv[w] = mn;
    __syncthreads();
    if (tid == 0) {
        float t = swv[0];
        for (int i = 1; i < 8; i++) t = fminf(t, swv[i]);
        out[b] = t;
    }
}

// ---------------------------------------------------------------------------
extern "C" void kernel_launch(void* const* d_in, const int* in_sizes, int n_in,
                              void* d_out, int out_size) {
    const float* pred = (const float*)d_in[0];
    const float* W    = (const float*)d_in[1];
    const float* K    = (const float*)d_in[2];
    float* out = (float*)d_out;

    convert_kernel<<<CP, 256>>>(W);
    gram_mma_kernel<<<NPAIRS, 256>>>(K);
    fused_final_kernel<<<NB, 256>>>(pred, out);
}